// round 11
// baseline (speedup 1.0000x reference)
#include <cuda_runtime.h>
#include <cstdint>

#define M_NODES 150000
#define KNN 64
#define KNN_ELEMS (M_NODES * KNN)                 // 9,600,000
#define CHUNK 16384
#define NCHUNK ((M_NODES + CHUNK - 1) / CHUNK)   // 10
#define NB 148
#define TPB 256
#define NWARPS (NB * (TPB / 32))                  // 1184

// Input:  knn int32 [150000 x 64]
// Output: float32 x 9,750,000 = [kept (0.0/1.0) x 150000][kept_knn (float) x 9,600,000]

// Scratch (allocation-free: __device__ globals).
__device__ unsigned short g_preds[2][CHUNK * KNN];
__device__ unsigned char  g_cnt[2][CHUNK];
__device__ unsigned char  g_ext[2][CHUNK];
__device__ unsigned       g_count;
__device__ unsigned       g_sense;

#define SH_KEEP_BYTES 150016
#define SMEM_BYTES (SH_KEEP_BYTES + CHUNK + 64)

__global__ void nms_init_kernel() { g_count = 0; g_sense = 0; }

__device__ __forceinline__ void grid_sync(unsigned target) {
    __syncthreads();
    if (threadIdx.x == 0) {
        __threadfence();
        unsigned old = atomicAdd(&g_count, 1);
        if (old == NB - 1) {
            atomicExch(&g_count, 0);
            __threadfence();
            atomicExch(&g_sense, target);
        } else {
            while (atomicAdd(&g_sense, 0) < target) __nanosleep(64);
            __threadfence();
        }
    }
    __syncthreads();
}

__global__ __launch_bounds__(TPB, 1)
void nms_main_kernel(const int* __restrict__ knn, float* __restrict__ out)
{
    extern __shared__ unsigned char smem[];
    unsigned char* sh_keep = smem;                       // final keep per node
    unsigned char* st      = smem + SH_KEEP_BYTES;       // 0 undec, 2 drop, 3 keep
    unsigned* sh_undec     = (unsigned*)(smem + SH_KEEP_BYTES + CHUNK);

    const int tid  = threadIdx.x;
    const int lane = tid & 31;
    const int wg   = blockIdx.x * (TPB / 32) + (tid >> 5);
    const unsigned FULL = 0xffffffffu;
    const unsigned lt   = (1u << lane) - 1u;

    for (int c = 0; c < NCHUNK; c++) {
        const int cs  = c * CHUNK;
        const int ce  = (cs + CHUNK < M_NODES) ? cs + CHUNK : M_NODES;
        const int csz = ce - cs;
        const int b   = c & 1;

        // ---- Phase 1: ext-check + in-chunk pred-list build (grid-parallel) ----
        for (int node = cs + wg; node < ce; node += NWARPS) {
            const int* row = knn + (size_t)node * KNN;
            int a0 = row[lane];
            int a1 = row[lane + 32];
            bool e0 = (a0 < cs) ? (sh_keep[a0] != 0) : false;
            bool e1 = (a1 < cs) ? (sh_keep[a1] != 0) : false;
            unsigned extm = __ballot_sync(FULL, e0 | e1);
            int li = node - cs;
            if (extm) {
                if (lane == 0) g_ext[b][li] = 1;      // dropped by earlier chunks
            } else {
                bool p0 = (a0 >= cs) && (a0 < node);
                bool p1 = (a1 >= cs) && (a1 < node);
                unsigned m0 = __ballot_sync(FULL, p0);
                unsigned m1 = __ballot_sync(FULL, p1);
                unsigned short* pl = &g_preds[b][(size_t)li * KNN];
                if (p0) pl[__popc(m0 & lt)] = (unsigned short)(a0 - cs);
                int c0 = __popc(m0);
                if (p1) pl[c0 + __popc(m1 & lt)] = (unsigned short)(a1 - cs);
                if (lane == 0) {
                    g_cnt[b][li] = (unsigned char)(c0 + __popc(m1));
                    g_ext[b][li] = 0;
                }
            }
        }

        grid_sync((unsigned)(c + 1));   // one barrier per chunk

        // ---- Resolution: every block redundantly resolves the chunk DAG ----
        for (int li = tid; li < csz; li += TPB) {
            unsigned char s;
            if (g_ext[b][li]) s = 2;
            else s = (g_cnt[b][li] == 0) ? (unsigned char)3 : (unsigned char)0;
            st[li] = s;
        }

        for (;;) {
            __syncthreads();
            if (tid == 0) *sh_undec = 0;
            __syncthreads();
            unsigned my = 0;
            for (int li = tid; li < csz; li += TPB) {
                if (st[li]) continue;
                int n = g_cnt[b][li];
                const unsigned short* pl = &g_preds[b][(size_t)li * KNN];
                unsigned char ns = 3;   // tentative KEEP
                for (int j = 0; j < n; j++) {
                    unsigned char ps = st[pl[j]];
                    if (ps == 3) { ns = 2; break; }   // kept pred -> drop
                    if (ps == 0) { ns = 0; break; }   // undecided pred -> wait
                }
                if (ns) st[li] = ns; else my++;
            }
            if (my) atomicAdd(sh_undec, my);
            __syncthreads();
            if (*sh_undec == 0) break;
        }

        // commit chunk verdicts into this block's keep array
        __syncthreads();
        for (int li = tid; li < csz; li += TPB)
            sh_keep[cs + li] = (st[li] == 3) ? 1 : 0;
        __syncthreads();
        // no grid barrier here: next phase1 reads only this block's smem,
        // and phase1 writes go to the other scratch buffer (double-buffered).
    }

    // ---- Output pass: float32 [kept at 0 .. 150000)[kept_knn at 150000 ..) ----
    float* knn_out = out + M_NODES;
    for (int node = wg; node < M_NODES; node += NWARPS) {
        int kb = (int)sh_keep[node];
        const int* row = knn + (size_t)node * KNN;
        int v0 = row[lane];
        int v1 = row[lane + 32];
        float* orow = knn_out + (size_t)node * KNN;
        orow[lane]      = (float)(kb ? v0 : M_NODES);
        orow[lane + 32] = (float)(kb ? v1 : M_NODES);
        if (lane == 0) out[node] = (float)kb;
    }
}

extern "C" void kernel_launch(void* const* d_in, const int* in_sizes, int n_in,
                              void* d_out, int out_size)
{
    // Find the knn input by element count (robust to input ordering).
    const int* knn = nullptr;
    for (int i = 0; i < n_in; i++)
        if (in_sizes[i] == KNN_ELEMS) { knn = (const int*)d_in[i]; break; }
    if (!knn) knn = (const int*)d_in[n_in - 1];

    cudaFuncSetAttribute(nms_main_kernel,
                         cudaFuncAttributeMaxDynamicSharedMemorySize, SMEM_BYTES);

    nms_init_kernel<<<1, 1>>>();
    nms_main_kernel<<<NB, TPB, SMEM_BYTES>>>(knn, (float*)d_out);
}

// round 13
// speedup vs baseline: 1.8258x; 1.8258x over previous
#include <cuda_runtime.h>
#include <cstdint>

#define M_NODES 150000
#define KNN 64
#define KNN_ELEMS (M_NODES * KNN)                 // 9,600,000
#define CHUNK 16384
#define NCHUNK ((M_NODES + CHUNK - 1) / CHUNK)   // 10
#define NB 148
#define TPB 512
#define WPB (TPB / 32)                            // 16
#define NWARPS (NB * WPB)                         // 2368
#define SUB 2048
#define NSUB (CHUNK / SUB)                        // 8
#define NPT (SUB / TPB)                           // 4 nodes/thread per sub
#define KEEPW 4704                                // u32 words (>= 150016 bits)

// Output: float32 [kept (0/1) x 150000][kept_knn x 9,600,000]

// Scratch (allocation-free __device__ globals), double-buffered per chunk.
__device__ unsigned short g_preds[2][CHUNK][KNN]; // in-chunk pred offsets (u16)
__device__ unsigned char  g_meta[2][CHUNK];       // 0x80 = ext-drop, else pred count
__device__ unsigned       g_count;
__device__ unsigned       g_sense;

__global__ void nms_init_kernel() { g_count = 0; g_sense = 0; }

__device__ __forceinline__ void grid_sync(unsigned target) {
    __syncthreads();
    if (threadIdx.x == 0) {
        __threadfence();
        unsigned old = atomicAdd(&g_count, 1);
        if (old == NB - 1) {
            atomicExch(&g_count, 0);
            __threadfence();
            atomicExch(&g_sense, target);
        } else {
            while (atomicAdd(&g_sense, 0) < target) __nanosleep(32);
            __threadfence();
        }
    }
    __syncthreads();
}

__global__ __launch_bounds__(TPB, 1)
void nms_main_kernel(const int* __restrict__ knn, float* __restrict__ out)
{
    __shared__ unsigned      keepw[KEEPW];   // keep bitmap, identical in every block
    __shared__ unsigned char st[CHUNK];      // 0 undec, 2 drop, 3 keep
    __shared__ unsigned      sh_undec;

    const int tid  = threadIdx.x;
    const int lane = tid & 31;
    const int wg   = blockIdx.x * WPB + (tid >> 5);
    const unsigned FULL = 0xffffffffu;
    const unsigned lt   = (1u << lane) - 1u;

    for (int i = tid; i < KEEPW; i += TPB) keepw[i] = 0;
    __syncthreads();

    for (int c = 0; c < NCHUNK; c++) {
        const int cs  = c * CHUNK;
        const int ce  = (cs + CHUNK < M_NODES) ? cs + CHUNK : M_NODES;
        const int csz = ce - cs;
        const int b   = c & 1;

        // ---- Phase 1 (grid-parallel): ext-check + pred-list build, 2 rows/iter ----
        for (int base = cs + wg * 2; base < ce; base += NWARPS * 2) {
            const int* r0 = knn + (size_t)base * KNN;
            const int* r1 = r0 + KNN;
            // 4 independent loads in flight before any dependent work
            int a0 = r0[lane], a1 = r0[lane + 32];
            int b0 = r1[lane], b1 = r1[lane + 32];

            bool e0 = (a0 < cs) && ((keepw[a0 >> 5] >> (a0 & 31)) & 1u);
            bool e1 = (a1 < cs) && ((keepw[a1 >> 5] >> (a1 & 31)) & 1u);
            bool f0 = (b0 < cs) && ((keepw[b0 >> 5] >> (b0 & 31)) & 1u);
            bool f1 = (b1 < cs) && ((keepw[b1 >> 5] >> (b1 & 31)) & 1u);
            unsigned ext0 = __ballot_sync(FULL, e0 | e1);
            unsigned ext1 = __ballot_sync(FULL, f0 | f1);

            {   // node base
                int li = base - cs;
                if (ext0) {
                    if (lane == 0) g_meta[b][li] = 0x80;
                } else {
                    bool p0 = (a0 >= cs) && (a0 < base);
                    bool p1 = (a1 >= cs) && (a1 < base);
                    unsigned m0 = __ballot_sync(FULL, p0);
                    unsigned m1 = __ballot_sync(FULL, p1);
                    unsigned short* pl = g_preds[b][li];
                    if (p0) pl[__popc(m0 & lt)] = (unsigned short)(a0 - cs);
                    int c0 = __popc(m0);
                    if (p1) pl[c0 + __popc(m1 & lt)] = (unsigned short)(a1 - cs);
                    if (lane == 0) g_meta[b][li] = (unsigned char)(c0 + __popc(m1));
                }
            }
            {   // node base+1
                int li = base + 1 - cs;
                if (ext1) {
                    if (lane == 0) g_meta[b][li] = 0x80;
                } else {
                    bool p0 = (b0 >= cs) && (b0 < base + 1);
                    bool p1 = (b1 >= cs) && (b1 < base + 1);
                    unsigned m0 = __ballot_sync(FULL, p0);
                    unsigned m1 = __ballot_sync(FULL, p1);
                    unsigned short* pl = g_preds[b][li];
                    if (p0) pl[__popc(m0 & lt)] = (unsigned short)(b0 - cs);
                    int c0 = __popc(m0);
                    if (p1) pl[c0 + __popc(m1 & lt)] = (unsigned short)(b1 - cs);
                    if (lane == 0) g_meta[b][li] = (unsigned char)(c0 + __popc(m1));
                }
            }
        }

        grid_sync((unsigned)(c + 1));   // one grid barrier per chunk

        // ---- st init from meta (coalesced u32 loads, vector STS) ----
        const unsigned* mw = (const unsigned*)g_meta[b];
        for (int w = tid; w < CHUNK / 4; w += TPB) {
            unsigned m = mw[w];
            unsigned sv = 0;
            #pragma unroll
            for (int k = 0; k < 4; k++) {
                unsigned mb = (m >> (8 * k)) & 0xffu;
                unsigned sb;
                if (w * 4 + k >= csz) sb = 2;                 // out of range: decided-drop
                else if (mb & 0x80u)  sb = 2;                 // ext-dropped
                else if (mb == 0)     sb = 3;                 // no preds: keep
                else                  sb = 0;                 // undecided
                sv |= sb << (8 * k);
            }
            ((unsigned*)st)[w] = sv;
        }
        __syncthreads();

        // ---- Resolution: ordered sub-chunks; preds cached in registers ----
        for (int s = 0; s < NSUB; s++) {
            const int s0  = s * SUB;
            const int li0 = s0 + tid * NPT;

            // fetch cnt (one u32 = 4 meta bytes) + first 8 preds per undecided node
            unsigned mword = mw[li0 >> 2];
            int   pcnt[NPT];
            uint4 pc[NPT];
            #pragma unroll
            for (int k = 0; k < NPT; k++) {
                pcnt[k] = (mword >> (8 * k)) & 0x7f;
                if (st[li0 + k] == 0 && pcnt[k] > 0)
                    pc[k] = *(const uint4*)g_preds[b][li0 + k];
            }

            for (;;) {
                __syncthreads();
                if (tid == 0) sh_undec = 0;
                __syncthreads();
                unsigned mine = 0;
                #pragma unroll
                for (int k = 0; k < NPT; k++) {
                    int li = li0 + k;
                    if (st[li] != 0) continue;
                    int n = pcnt[k];
                    bool undec = false, drop = false;
                    unsigned pw[4] = {pc[k].x, pc[k].y, pc[k].z, pc[k].w};
                    int n8 = n < 8 ? n : 8;
                    for (int j = 0; j < n8; j++) {
                        unsigned v  = (pw[j >> 1] >> ((j & 1) * 16)) & 0xffffu;
                        unsigned char ps = st[v];
                        if (ps == 3) { drop = true; break; }
                        if (ps == 0) undec = true;
                    }
                    if (!drop && n > 8) {   // rare overflow (~1% of nodes)
                        const unsigned short* pl = g_preds[b][li];
                        for (int j = 8; j < n; j++) {
                            unsigned char ps = st[pl[j]];
                            if (ps == 3) { drop = true; break; }
                            if (ps == 0) undec = true;
                        }
                    }
                    if (drop)       st[li] = 2;
                    else if (!undec) st[li] = 3;
                    else mine++;
                }
                if (mine) atomicAdd(&sh_undec, mine);
                __syncthreads();
                if (sh_undec == 0) break;
            }
        }

        // ---- Commit chunk verdicts into the keep bitmap (warp ballots) ----
        __syncthreads();
        for (int base2 = (tid >> 5) * 32; base2 < csz; base2 += WPB * 32) {
            int li = base2 + lane;
            bool kk = (li < csz) && (st[li] == 3);
            unsigned wbits = __ballot_sync(FULL, kk);
            if (lane == 0) keepw[(cs + base2) >> 5] = wbits;
        }
        __syncthreads();
        // no grid barrier here: next phase1 reads only local smem; scratch is
        // double-buffered, and no block can get >1 chunk ahead (phase-1 barrier).
    }

    // ---- Output pass: float32 [kept][kept_knn] ----
    float* knn_out = out + M_NODES;
    for (int node = wg; node < M_NODES; node += NWARPS) {
        int kb = (keepw[node >> 5] >> (node & 31)) & 1u;
        const int* row = knn + (size_t)node * KNN;
        int v0 = row[lane];
        int v1 = row[lane + 32];
        float* orow = knn_out + (size_t)node * KNN;
        orow[lane]      = (float)(kb ? v0 : M_NODES);
        orow[lane + 32] = (float)(kb ? v1 : M_NODES);
    }
    for (int i = wg * 32 + lane; i < M_NODES; i += NWARPS * 32)
        out[i] = ((keepw[i >> 5] >> (i & 31)) & 1u) ? 1.0f : 0.0f;
}

extern "C" void kernel_launch(void* const* d_in, const int* in_sizes, int n_in,
                              void* d_out, int out_size)
{
    const int* knn = nullptr;
    for (int i = 0; i < n_in; i++)
        if (in_sizes[i] == KNN_ELEMS) { knn = (const int*)d_in[i]; break; }
    if (!knn) knn = (const int*)d_in[n_in - 1];

    nms_init_kernel<<<1, 1>>>();
    nms_main_kernel<<<NB, TPB>>>(knn, (float*)d_out);
}

// round 17
// speedup vs baseline: 2.2556x; 1.2354x over previous
#include <cuda_runtime.h>
#include <cstdint>

#define M_NODES 150000
#define KNN 64
#define KNN_ELEMS (M_NODES * KNN)                 // 9,600,000
#define CHUNK 16384
#define NCHUNK ((M_NODES + CHUNK - 1) / CHUNK)   // 10
#define NB 148
#define TPB 512
#define WPB (TPB / 32)                            // 16
#define NWARPS (NB * WPB)                         // 2368
#define SUB 2048
#define NSUB (CHUNK / SUB)                        // 8
#define NPT (SUB / TPB)                           // 4 nodes/thread per sub
#define KEEPW 4704                                // u32 words (>= 150016 bits)

// Output: float32 [kept (0/1) x 150000][kept_knn x 9,600,000]

// Scratch (allocation-free __device__ globals), double-buffered per chunk.
__device__ unsigned short g_preds[2][CHUNK][KNN]; // in-chunk pred offsets (u16)
__device__ unsigned char  g_meta[2][CHUNK];       // 0x80 = ext-drop, else pred count
__device__ unsigned       g_count;
__device__ unsigned       g_sense;

__global__ void nms_init_kernel() { g_count = 0; g_sense = 0; }

__device__ __forceinline__ void grid_sync(unsigned target) {
    __syncthreads();
    if (threadIdx.x == 0) {
        __threadfence();
        unsigned old = atomicAdd(&g_count, 1);
        if (old == NB - 1) {
            atomicExch(&g_count, 0);
            __threadfence();
            atomicExch(&g_sense, target);
        } else {
            while (*(volatile unsigned*)&g_sense < target) __nanosleep(64);
            __threadfence();
        }
    }
    __syncthreads();
}

__global__ __launch_bounds__(TPB, 1)
void nms_main_kernel(const int* __restrict__ knn, float* __restrict__ out)
{
    __shared__ unsigned      keepw[KEEPW];   // keep bitmap, identical in every block
    __shared__ unsigned char st[CHUNK];      // 0 undec, 2 drop, 3 keep

    const int tid  = threadIdx.x;
    const int lane = tid & 31;
    const int wg   = blockIdx.x * WPB + (tid >> 5);
    const unsigned FULL = 0xffffffffu;
    const unsigned lt   = (1u << lane) - 1u;

    for (int i = tid; i < KEEPW; i += TPB) keepw[i] = 0;
    __syncthreads();

    for (int c = 0; c < NCHUNK; c++) {
        const int cs  = c * CHUNK;
        const int ce  = (cs + CHUNK < M_NODES) ? cs + CHUNK : M_NODES;
        const int csz = ce - cs;
        const int b   = c & 1;

        // ---- Phase 1 (grid-parallel): 4 rows/iteration, 8 loads in flight ----
        for (int base = cs + wg * 4; base < ce; base += NWARPS * 4) {
            const int nr = (ce - base < 4) ? (ce - base) : 4;
            int a[4][2];
            #pragma unroll
            for (int r = 0; r < 4; r++) {
                if (r < nr) {
                    const int* row = knn + (size_t)(base + r) * KNN;
                    a[r][0] = __ldg(row + lane);
                    a[r][1] = __ldg(row + lane + 32);
                }
            }
            #pragma unroll
            for (int r = 0; r < 4; r++) {
                if (r >= nr) break;
                const int node = base + r;
                const int li   = node - cs;
                const int a0 = a[r][0], a1 = a[r][1];
                bool e0 = (a0 < cs) && ((keepw[a0 >> 5] >> (a0 & 31)) & 1u);
                bool e1 = (a1 < cs) && ((keepw[a1 >> 5] >> (a1 & 31)) & 1u);
                unsigned extm = __ballot_sync(FULL, e0 | e1);
                if (extm) {
                    if (lane == 0) g_meta[b][li] = 0x80;
                } else {
                    bool p0 = (a0 >= cs) && (a0 < node);
                    bool p1 = (a1 >= cs) && (a1 < node);
                    unsigned m0 = __ballot_sync(FULL, p0);
                    unsigned m1 = __ballot_sync(FULL, p1);
                    unsigned short* pl = g_preds[b][li];
                    if (p0) pl[__popc(m0 & lt)] = (unsigned short)(a0 - cs);
                    int c0 = __popc(m0);
                    if (p1) pl[c0 + __popc(m1 & lt)] = (unsigned short)(a1 - cs);
                    if (lane == 0) g_meta[b][li] = (unsigned char)(c0 + __popc(m1));
                }
            }
        }

        grid_sync((unsigned)(c + 1));   // one grid barrier per chunk

        // ---- st init from meta (coalesced u32 loads, vector STS) ----
        const unsigned* mw = (const unsigned*)g_meta[b];
        for (int w = tid; w < CHUNK / 4; w += TPB) {
            unsigned m = mw[w];
            unsigned sv = 0;
            #pragma unroll
            for (int k = 0; k < 4; k++) {
                unsigned mb = (m >> (8 * k)) & 0xffu;
                unsigned sb;
                if (w * 4 + k >= csz) sb = 2;                 // out of range: drop
                else if (mb & 0x80u)  sb = 2;                 // ext-dropped
                else if (mb == 0)     sb = 3;                 // no preds: keep
                else                  sb = 0;                 // undecided
                sv |= sb << (8 * k);
            }
            ((unsigned*)st)[w] = sv;
        }
        __syncthreads();

        // ---- Resolution: ordered sub-chunks; first 16 preds cached in regs ----
        for (int s = 0; s < NSUB; s++) {
            const int li0 = s * SUB + tid * NPT;

            unsigned mword = mw[li0 >> 2];
            int   pcnt[NPT];
            uint4 pcA[NPT], pcB[NPT];
            #pragma unroll
            for (int k = 0; k < NPT; k++) {
                pcnt[k] = (mword >> (8 * k)) & 0x7f;
                if (st[li0 + k] == 0 && pcnt[k] > 0) {
                    const uint4* pp = (const uint4*)g_preds[b][li0 + k];
                    pcA[k] = pp[0];
                    if (pcnt[k] > 8) pcB[k] = pp[1];
                }
            }

            for (;;) {
                unsigned mine = 0;
                #pragma unroll
                for (int k = 0; k < NPT; k++) {
                    const int li = li0 + k;
                    if (st[li] != 0) continue;
                    const int n = pcnt[k];
                    bool undec = false, drop = false;
                    unsigned pw[8] = {pcA[k].x, pcA[k].y, pcA[k].z, pcA[k].w,
                                      pcB[k].x, pcB[k].y, pcB[k].z, pcB[k].w};
                    const int n16 = n < 16 ? n : 16;
                    for (int j = 0; j < n16; j++) {
                        unsigned v = (pw[j >> 1] >> ((j & 1) * 16)) & 0xffffu;
                        unsigned char ps = st[v];
                        if (ps == 3) { drop = true; break; }
                        if (ps == 0) undec = true;
                    }
                    if (!drop && n > 16) {   // very rare (P ~ 1e-3)
                        const unsigned short* pl = g_preds[b][li];
                        for (int j = 16; j < n; j++) {
                            unsigned char ps = st[pl[j]];
                            if (ps == 3) { drop = true; break; }
                            if (ps == 0) undec = true;
                        }
                    }
                    if (drop)        st[li] = 2;
                    else if (!undec) st[li] = 3;
                    else mine = 1;
                }
                // single barrier per sweep; st writes/reads race is benign
                // (state is monotone 0 -> {2,3}; stale 0 just means one more sweep)
                if (__syncthreads_count(mine) == 0) break;
            }
        }

        // ---- Commit chunk verdicts into the keep bitmap (warp ballots) ----
        __syncthreads();
        for (int base2 = (tid >> 5) * 32; base2 < csz; base2 += WPB * 32) {
            int li = base2 + lane;
            bool kk = (li < csz) && (st[li] == 3);
            unsigned wbits = __ballot_sync(FULL, kk);
            if (lane == 0) keepw[(cs + base2) >> 5] = wbits;
        }
        __syncthreads();
        // no grid barrier here: next phase1 reads only local smem; scratch is
        // double-buffered, and no block can get >1 chunk ahead (phase-1 barrier).
    }

    // ---- Output pass: float32 [kept][kept_knn] ----
    float* knn_out = out + M_NODES;
    for (int node = wg; node < M_NODES; node += NWARPS) {
        int kb = (keepw[node >> 5] >> (node & 31)) & 1u;
        const int* row = knn + (size_t)node * KNN;
        int v0 = __ldg(row + lane);
        int v1 = __ldg(row + lane + 32);
        float* orow = knn_out + (size_t)node * KNN;
        orow[lane]      = (float)(kb ? v0 : M_NODES);
        orow[lane + 32] = (float)(kb ? v1 : M_NODES);
    }
    for (int i = wg * 32 + lane; i < M_NODES; i += NWARPS * 32)
        out[i] = ((keepw[i >> 5] >> (i & 31)) & 1u) ? 1.0f : 0.0f;
}

extern "C" void kernel_launch(void* const* d_in, const int* in_sizes, int n_in,
                              void* d_out, int out_size)
{
    const int* knn = nullptr;
    for (int i = 0; i < n_in; i++)
        if (in_sizes[i] == KNN_ELEMS) { knn = (const int*)d_in[i]; break; }
    if (!knn) knn = (const int*)d_in[n_in - 1];

    nms_init_kernel<<<1, 1>>>();
    nms_main_kernel<<<NB, TPB>>>(knn, (float*)d_out);
}